// round 13
// baseline (speedup 1.0000x reference)
#include <cuda_runtime.h>

// IAF spiking layer forward; vmem matches XLA ReduceWindowRewriter's scan
// association (base_length = 16) for cumsum over T=512 — verified bitwise
// (R8/R10/R11/R12: rel_err == 0.0). Arithmetic identical to R8.
//
//   i = 16k + c,  k = 16s + r
//   I[i]   = sequential prefix of x within block k        (leading 0 exact)
//   SPin_k = sequential prefix of block totals within superblock s
//   C_k    = add(ET_s, SPin_k), ET_s in {0, U0}
//   vmem[i] = add(C_{k-1}, I[i])
//   s_t = ((vmem_t - sub) - 1.0 >= 0);  sub += s_t   (sub integer-exact)
//
// R13: software-pipelined loads on top of R12's forced-asm MLP.
// Block k+1's 16 loads issue BEFORE block k's spike chain consumes its
// (already in-flight) data -> each load gets a full block of slack ->
// warps nearly expose-free, kernel purely DRAM-throughput-bound.
// 2x16 load regs + state ~= 50 regs; 28 warps/SM preserved.

#define T_SIM 512
#define FEAT  8192

__device__ __forceinline__ float ldg_cs(const float* p)
{
    float v;
    asm volatile("ld.global.cs.f32 %0, [%1];" : "=f"(v) : "l"(p));
    return v;
}

__global__ __launch_bounds__(128)
void iaf_kernel(const float* __restrict__ x, float* __restrict__ out)
{
    const int f = blockIdx.x * blockDim.x + threadIdx.x;
    const int b = blockIdx.y;

    const long long base = (long long)b * T_SIM * FEAT + f;
    const float* __restrict__ xp = x + base;
    float* __restrict__ op = out + base;

    float E    = 0.0f;   // exclusive block prefix (C_{k-1})
    float ET   = 0.0f;   // exclusive superblock prefix (0, then U0)
    float SPin = 0.0f;   // sequential fold of block totals in superblock
    float sub  = 0.0f;   // accumulated membrane subtraction (integer-exact)

    float xv[2][16];     // double-buffered in-flight loads

    // prologue: prefetch block 0
    #pragma unroll
    for (int c = 0; c < 16; ++c)
        xv[0][c] = ldg_cs(xp + c * FEAT);

    #pragma unroll 2
    for (int k = 0; k < 32; ++k) {
        const int cur = k & 1;
        float* ob = op + (long long)k * 16 * FEAT;

        // prefetch block k+1 before consuming block k
        if (k < 31) {
            const float* xn = xp + (long long)(k + 1) * 16 * FEAT;
            #pragma unroll
            for (int c = 0; c < 16; ++c)
                xv[cur ^ 1][c] = ldg_cs(xn + c * FEAT);
        }

        // serial spike chain (identical fp order to R8)
        float I = 0.0f;
        #pragma unroll
        for (int c = 0; c < 16; ++c) {
            I = I + xv[cur][c];                  // leading 0+x exact
            float v = E + I;
            float u = (v - sub) - 1.0f;
            float s = (u >= 0.0f) ? 1.0f : 0.0f;
            sub += s;
            __stcs(ob + c * FEAT, s);
        }

        // block boundary: T_k = I
        SPin = SPin + I;
        if (k == 15) {
            ET   = SPin;                         // U0 = C_15
            E    = ET;
            SPin = 0.0f;
        } else {
            E = ET + SPin;                       // C_k = add(ET, SPin)
        }
    }
}

extern "C" void kernel_launch(void* const* d_in, const int* in_sizes, int n_in,
                              void* d_out, int out_size)
{
    const float* x = (const float*)d_in[0];
    float* out = (float*)d_out;

    int total = in_sizes[0];
    int batch = total / (T_SIM * FEAT);

    dim3 block(128, 1, 1);
    dim3 grid(FEAT / 128, batch, 1);             // 64 x 16 = 1024 CTAs
    iaf_kernel<<<grid, block>>>(x, out);
}

// round 14
// speedup vs baseline: 1.0291x; 1.0291x over previous
#include <cuda_runtime.h>

// IAF spiking layer forward; vmem matches XLA ReduceWindowRewriter's scan
// association (base_length = 16) for cumsum over T=512 — verified bitwise
// (R8/R10/R11/R12/R13: rel_err == 0.0). Arithmetic identical to R8.
//
//   i = 16k + c,  k = 16s + r
//   I[i]   = sequential prefix of x within block k        (leading 0 exact)
//   SPin_k = sequential prefix of block totals within superblock s
//   C_k    = add(ET_s, SPin_k), ET_s in {0, U0}
//   vmem[i] = add(C_{k-1}, I[i])
//   s_t = ((vmem_t - sub) - 1.0 >= 0);  sub += s_t   (sub integer-exact)
//
// R14: read/write burst separation. R13 proved loads are fully covered
// (double-buffer changed nothing), so the residual limiter is write-side.
// Per 16-step block: 16 pinned LDGs back-to-back -> spike chain into a
// spike reg array -> 16 pinned STGs back-to-back. Each warp now presents
// coarse 2KB same-direction bursts to DRAM instead of interleaved R/W.
// No double buffer (regs ~48, keeps wall/ncu overhead gap small).

#define T_SIM 512
#define FEAT  8192

__device__ __forceinline__ float ldg_cs(const float* p)
{
    float v;
    asm volatile("ld.global.cs.f32 %0, [%1];" : "=f"(v) : "l"(p));
    return v;
}

__device__ __forceinline__ void stg_cs(float* p, float v)
{
    asm volatile("st.global.cs.f32 [%0], %1;" :: "l"(p), "f"(v) : "memory");
}

__global__ __launch_bounds__(128)
void iaf_kernel(const float* __restrict__ x, float* __restrict__ out)
{
    const int f = blockIdx.x * blockDim.x + threadIdx.x;
    const int b = blockIdx.y;

    const long long base = (long long)b * T_SIM * FEAT + f;
    const float* __restrict__ xp = x + base;
    float* __restrict__ op = out + base;

    float E    = 0.0f;   // exclusive block prefix (C_{k-1})
    float ET   = 0.0f;   // exclusive superblock prefix (0, then U0)
    float SPin = 0.0f;   // sequential fold of block totals in superblock
    float sub  = 0.0f;   // accumulated membrane subtraction (integer-exact)

    for (int k = 0; k < 32; ++k) {               // 32 blocks of 16 timesteps
        const float* xb = xp + (long long)k * 16 * FEAT;
        float* ob = op + (long long)k * 16 * FEAT;

        // ---- read burst: 16 pinned LDGs back-to-back ----
        float xv[16];
        #pragma unroll
        for (int c = 0; c < 16; ++c)
            xv[c] = ldg_cs(xb + c * FEAT);

        // ---- serial spike chain (identical fp order to R8) ----
        float sv[16];
        float I = 0.0f;
        #pragma unroll
        for (int c = 0; c < 16; ++c) {
            I = I + xv[c];                       // leading 0+x exact
            float v = E + I;
            float u = (v - sub) - 1.0f;
            float s = (u >= 0.0f) ? 1.0f : 0.0f;
            sub += s;
            sv[c] = s;
        }

        // ---- write burst: 16 pinned STGs back-to-back ----
        #pragma unroll
        for (int c = 0; c < 16; ++c)
            stg_cs(ob + c * FEAT, sv[c]);

        // block boundary: T_k = I
        SPin = SPin + I;
        if (k == 15) {
            ET   = SPin;                         // U0 = C_15
            E    = ET;
            SPin = 0.0f;
        } else {
            E = ET + SPin;                       // C_k = add(ET, SPin)
        }
    }
}

extern "C" void kernel_launch(void* const* d_in, const int* in_sizes, int n_in,
                              void* d_out, int out_size)
{
    const float* x = (const float*)d_in[0];
    float* out = (float*)d_out;

    int total = in_sizes[0];
    int batch = total / (T_SIM * FEAT);

    dim3 block(128, 1, 1);
    dim3 grid(FEAT / 128, batch, 1);             // 64 x 16 = 1024 CTAs
    iaf_kernel<<<grid, block>>>(x, out);
}

// round 15
// speedup vs baseline: 1.0477x; 1.0181x over previous
#include <cuda_runtime.h>

// IAF spiking layer forward; vmem matches XLA ReduceWindowRewriter's scan
// association (base_length = 16) for cumsum over T=512 — verified bitwise
// (R8/R10/R11/R12/R13/R14: rel_err == 0.0). Arithmetic identical to R8.
//
//   i = 16k + c,  k = 16s + r
//   I[i]   = sequential prefix of x within block k        (leading 0 exact)
//   SPin_k = sequential prefix of block totals within superblock s
//   C_k    = add(ET_s, SPin_k), ET_s in {0, U0}
//   vmem[i] = add(C_{k-1}, I[i])
//   s_t = ((vmem_t - sub) - 1.0 >= 0);  sub += s_t   (sub integer-exact)
//
// R15: kernel time is at the mixed-R/W HBM plateau (~6.1 TB/s; prefetch and
// burst-separation both neutral). Remaining lever is per-replay launch
// overhead, measured ~3.5us lower for 512-CTA than 1024-CTA launches.
// This round: R12's pinned-load body (forced asm MLP, .cs hints, 32 regs)
// at R8's 512 CTA x 256 thread geometry.

#define T_SIM 512
#define FEAT  8192

__device__ __forceinline__ float ldg_cs(const float* p)
{
    float v;
    asm volatile("ld.global.cs.f32 %0, [%1];" : "=f"(v) : "l"(p));
    return v;
}

__global__ __launch_bounds__(256)
void iaf_kernel(const float* __restrict__ x, float* __restrict__ out)
{
    const int f = blockIdx.x * blockDim.x + threadIdx.x;
    const int b = blockIdx.y;

    const long long base = (long long)b * T_SIM * FEAT + f;
    const float* __restrict__ xp = x + base;
    float* __restrict__ op = out + base;

    float E    = 0.0f;   // exclusive block prefix (C_{k-1})
    float ET   = 0.0f;   // exclusive superblock prefix (0, then U0)
    float SPin = 0.0f;   // sequential fold of block totals in superblock
    float sub  = 0.0f;   // accumulated membrane subtraction (integer-exact)

    for (int k = 0; k < 32; ++k) {               // 32 blocks of 16 timesteps
        const float* xb = xp + (long long)k * 16 * FEAT;
        float* ob = op + (long long)k * 16 * FEAT;

        // ---- 16 independent loads, pinned back-to-back in SASS ----
        float xv[16];
        #pragma unroll
        for (int c = 0; c < 16; ++c)
            xv[c] = ldg_cs(xb + c * FEAT);

        // ---- serial spike chain (identical fp order to R8) ----
        float I = 0.0f;
        #pragma unroll
        for (int c = 0; c < 16; ++c) {
            I = I + xv[c];                       // leading 0+x exact
            float v = E + I;
            float u = (v - sub) - 1.0f;
            float s = (u >= 0.0f) ? 1.0f : 0.0f;
            sub += s;
            __stcs(ob + c * FEAT, s);
        }

        // block boundary: T_k = I
        SPin = SPin + I;
        if (k == 15) {
            ET   = SPin;                         // U0 = C_15
            E    = ET;
            SPin = 0.0f;
        } else {
            E = ET + SPin;                       // C_k = add(ET, SPin)
        }
    }
}

extern "C" void kernel_launch(void* const* d_in, const int* in_sizes, int n_in,
                              void* d_out, int out_size)
{
    const float* x = (const float*)d_in[0];
    float* out = (float*)d_out;

    int total = in_sizes[0];
    int batch = total / (T_SIM * FEAT);

    dim3 block(256, 1, 1);
    dim3 grid(FEAT / 256, batch, 1);             // 32 x 16 = 512 CTAs
    iaf_kernel<<<grid, block>>>(x, out);
}

// round 16
// speedup vs baseline: 1.0615x; 1.0132x over previous
#include <cuda_runtime.h>

// IAF spiking layer forward; vmem matches XLA ReduceWindowRewriter's scan
// association (base_length = 16) for cumsum over T=512 — verified bitwise
// (R8/R10-R15: rel_err == 0.0). Arithmetic identical to R8.
//
//   i = 16k + c,  k = 16s + r
//   I[i]   = sequential prefix of x within block k        (leading 0 exact)
//   SPin_k = sequential prefix of block totals within superblock s
//   C_k    = add(ET_s, SPin_k), ET_s in {0, U0}
//   vmem[i] = add(C_{k-1}, I[i])
//   s_t = ((vmem_t - sub) - 1.0 >= 0);  sub += s_t   (sub integer-exact)
//
// R16: geometry sweep, low-CTA end. Kernel time is pinned at the mixed-R/W
// HBM plateau; wall time varies through per-replay overhead ~ +7ns/CTA.
// 256 CTAs x 512 threads: same 15.6% quantization as 512-CTA (2 vs 1.73),
// so kernel ~82-84us, but ~1.5-2us less replay overhead than R15.
// Body identical to R15 (pinned asm loads, .cs stores, 32 regs).

#define T_SIM 512
#define FEAT  8192

__device__ __forceinline__ float ldg_cs(const float* p)
{
    float v;
    asm volatile("ld.global.cs.f32 %0, [%1];" : "=f"(v) : "l"(p));
    return v;
}

__global__ __launch_bounds__(512)
void iaf_kernel(const float* __restrict__ x, float* __restrict__ out)
{
    const int f = blockIdx.x * blockDim.x + threadIdx.x;
    const int b = blockIdx.y;

    const long long base = (long long)b * T_SIM * FEAT + f;
    const float* __restrict__ xp = x + base;
    float* __restrict__ op = out + base;

    float E    = 0.0f;   // exclusive block prefix (C_{k-1})
    float ET   = 0.0f;   // exclusive superblock prefix (0, then U0)
    float SPin = 0.0f;   // sequential fold of block totals in superblock
    float sub  = 0.0f;   // accumulated membrane subtraction (integer-exact)

    for (int k = 0; k < 32; ++k) {               // 32 blocks of 16 timesteps
        const float* xb = xp + (long long)k * 16 * FEAT;
        float* ob = op + (long long)k * 16 * FEAT;

        // ---- 16 independent loads, pinned back-to-back in SASS ----
        float xv[16];
        #pragma unroll
        for (int c = 0; c < 16; ++c)
            xv[c] = ldg_cs(xb + c * FEAT);

        // ---- serial spike chain (identical fp order to R8) ----
        float I = 0.0f;
        #pragma unroll
        for (int c = 0; c < 16; ++c) {
            I = I + xv[c];                       // leading 0+x exact
            float v = E + I;
            float u = (v - sub) - 1.0f;
            float s = (u >= 0.0f) ? 1.0f : 0.0f;
            sub += s;
            __stcs(ob + c * FEAT, s);
        }

        // block boundary: T_k = I
        SPin = SPin + I;
        if (k == 15) {
            ET   = SPin;                         // U0 = C_15
            E    = ET;
            SPin = 0.0f;
        } else {
            E = ET + SPin;                       // C_k = add(ET, SPin)
        }
    }
}

extern "C" void kernel_launch(void* const* d_in, const int* in_sizes, int n_in,
                              void* d_out, int out_size)
{
    const float* x = (const float*)d_in[0];
    float* out = (float*)d_out;

    int total = in_sizes[0];
    int batch = total / (T_SIM * FEAT);

    dim3 block(512, 1, 1);
    dim3 grid(FEAT / 512, batch, 1);             // 16 x 16 = 256 CTAs
    iaf_kernel<<<grid, block>>>(x, out);
}

// round 17
// speedup vs baseline: 1.0757x; 1.0134x over previous
#include <cuda_runtime.h>

// IAF spiking layer forward; vmem matches XLA ReduceWindowRewriter's scan
// association (base_length = 16) for cumsum over T=512 — verified bitwise
// (R8/R10-R16: rel_err == 0.0). Arithmetic identical to R8.
//
//   i = 16k + c,  k = 16s + r
//   I[i]   = sequential prefix of x within block k        (leading 0 exact)
//   SPin_k = sequential prefix of block totals within superblock s
//   C_k    = add(ET_s, SPin_k), ET_s in {0, U0}
//   vmem[i] = add(C_{k-1}, I[i])
//   s_t = ((vmem_t - sub) - 1.0 >= 0);  sub += s_t   (sub integer-exact)
//
// R17: 128 CTAs x 1024 threads = exactly one thread per (b,f) sequence.
// <=1 CTA/SM -> zero CTA quantization (every resident CTA identical);
// fewest CTAs yet -> lowest per-replay overhead (~7ns/CTA trend).
// Chip-level DRAM plateau (~6.1TB/s) needs only ~27 B/cyc/SM from 128 SMs
// vs ~70 B/cyc LSU capability, so idling 20 SMs is free.
// Body identical to R16 (pinned asm loads, .cs stores, 32 regs).

#define T_SIM 512
#define FEAT  8192

__device__ __forceinline__ float ldg_cs(const float* p)
{
    float v;
    asm volatile("ld.global.cs.f32 %0, [%1];" : "=f"(v) : "l"(p));
    return v;
}

__global__ __launch_bounds__(1024)
void iaf_kernel(const float* __restrict__ x, float* __restrict__ out)
{
    const int f = blockIdx.x * blockDim.x + threadIdx.x;
    const int b = blockIdx.y;

    const long long base = (long long)b * T_SIM * FEAT + f;
    const float* __restrict__ xp = x + base;
    float* __restrict__ op = out + base;

    float E    = 0.0f;   // exclusive block prefix (C_{k-1})
    float ET   = 0.0f;   // exclusive superblock prefix (0, then U0)
    float SPin = 0.0f;   // sequential fold of block totals in superblock
    float sub  = 0.0f;   // accumulated membrane subtraction (integer-exact)

    for (int k = 0; k < 32; ++k) {               // 32 blocks of 16 timesteps
        const float* xb = xp + (long long)k * 16 * FEAT;
        float* ob = op + (long long)k * 16 * FEAT;

        // ---- 16 independent loads, pinned back-to-back in SASS ----
        float xv[16];
        #pragma unroll
        for (int c = 0; c < 16; ++c)
            xv[c] = ldg_cs(xb + c * FEAT);

        // ---- serial spike chain (identical fp order to R8) ----
        float I = 0.0f;
        #pragma unroll
        for (int c = 0; c < 16; ++c) {
            I = I + xv[c];                       // leading 0+x exact
            float v = E + I;
            float u = (v - sub) - 1.0f;
            float s = (u >= 0.0f) ? 1.0f : 0.0f;
            sub += s;
            __stcs(ob + c * FEAT, s);
        }

        // block boundary: T_k = I
        SPin = SPin + I;
        if (k == 15) {
            ET   = SPin;                         // U0 = C_15
            E    = ET;
            SPin = 0.0f;
        } else {
            E = ET + SPin;                       // C_k = add(ET, SPin)
        }
    }
}

extern "C" void kernel_launch(void* const* d_in, const int* in_sizes, int n_in,
                              void* d_out, int out_size)
{
    const float* x = (const float*)d_in[0];
    float* out = (float*)d_out;

    int total = in_sizes[0];
    int batch = total / (T_SIM * FEAT);

    dim3 block(1024, 1, 1);
    dim3 grid(FEAT / 1024, batch, 1);            // 8 x 16 = 128 CTAs
    iaf_kernel<<<grid, block>>>(x, out);
}